// round 5
// baseline (speedup 1.0000x reference)
#include <cuda_runtime.h>
#include <cuda_bf16.h>
#include <cstdint>
#include <math.h>

#define DIM_IN 2048
#define QDIM   2048
#define LATENT 1024
#define N_ROIS 4096
#define N_BANK 8192
#define LN_EPS 1e-5f

// ============================ static scratch ====================================
// int8 quantized operands (2 slices each)
__device__ int8_t g_qF1 [(size_t)N_ROIS * QDIM];    __device__ int8_t g_qF2 [(size_t)N_ROIS * QDIM];
__device__ int8_t g_qKB1[(size_t)N_BANK * DIM_IN];  __device__ int8_t g_qKB2[(size_t)N_BANK * DIM_IN];
#define WSZ ((size_t)LATENT * QDIM)
__device__ int8_t g_qW1 [6 * WSZ];                  __device__ int8_t g_qW2 [6 * WSZ];
__device__ int8_t g_qWf1[WSZ];                      __device__ int8_t g_qWf2[WSZ];
__device__ int8_t g_qQ1 [(size_t)2 * N_ROIS * LATENT]; __device__ int8_t g_qQ2 [(size_t)2 * N_ROIS * LATENT];
__device__ int8_t g_qK1 [(size_t)2 * N_BANK * LATENT]; __device__ int8_t g_qK2 [(size_t)2 * N_BANK * LATENT];
__device__ int8_t g_qV1 [(size_t)2 * LATENT * N_BANK]; __device__ int8_t g_qV2 [(size_t)2 * LATENT * N_BANK];
__device__ int8_t g_qE1 [(size_t)2 * N_ROIS * N_BANK]; __device__ int8_t g_qE2 [(size_t)2 * N_ROIS * N_BANK];
__device__ int8_t g_qX1 [(size_t)N_ROIS * LATENT];  __device__ int8_t g_qX2 [(size_t)N_ROIS * LATENT];
// f32 intermediates
__device__ float g_Qf [(size_t)2 * N_ROIS * LATENT];
__device__ float g_Kf [(size_t)2 * N_BANK * LATENT];
__device__ float g_Vtf[(size_t)2 * LATENT * N_BANK];
__device__ float g_S  [(size_t)2 * N_ROIS * N_BANK];
__device__ float g_F  [(size_t)2 * N_ROIS * LATENT];
// per-row scales
__device__ float g_sF[N_ROIS];
__device__ float g_sKB[N_BANK];
__device__ float g_sW[6 * LATENT];
__device__ float g_sWf[DIM_IN];
__device__ float g_sQ[2 * N_ROIS];
__device__ float g_sK[2 * N_BANK];
__device__ float g_sV[2 * LATENT];
__device__ float g_sE[2 * N_ROIS];      // = 1/(127*rsum)
__device__ float g_sX[N_ROIS];

// ============================ PTX helpers =======================================
__device__ __forceinline__ uint32_t smem_u32(const void* p) {
    uint32_t a;
    asm("{ .reg .u64 t; cvta.to.shared.u64 t, %1; cvt.u32.u64 %0, t; }" : "=r"(a) : "l"(p));
    return a;
}
__device__ __forceinline__ void cp_async16(uint32_t s, const void* g) {
    asm volatile("cp.async.cg.shared.global [%0], [%1], 16;\n" :: "r"(s), "l"(g));
}
#define CP_COMMIT() asm volatile("cp.async.commit_group;\n" ::: "memory")
#define CP_WAIT1()  asm volatile("cp.async.wait_group 1;\n" ::: "memory")

#define LDSM_X4(r, a)                                                               \
    asm volatile("ldmatrix.sync.aligned.m8n8.x4.shared.b16 {%0,%1,%2,%3}, [%4];"    \
        : "=r"((r)[0]), "=r"((r)[1]), "=r"((r)[2]), "=r"((r)[3]) : "r"(a))

#define MMA_S8(c, a, b0, b1)                                                        \
    asm volatile("mma.sync.aligned.m16n8k32.row.col.s32.s8.s8.s32 "                 \
        "{%0,%1,%2,%3}, {%4,%5,%6,%7}, {%8,%9}, {%0,%1,%2,%3};"                     \
        : "+r"((c)[0]), "+r"((c)[1]), "+r"((c)[2]), "+r"((c)[3])                    \
        : "r"((a)[0]), "r"((a)[1]), "r"((a)[2]), "r"((a)[3]), "r"(b0), "r"(b1))

__device__ __forceinline__ uint32_t pack4(int a, int b, int c, int d) {
    return (uint32_t)(a & 255) | ((uint32_t)(b & 255) << 8) |
           ((uint32_t)(c & 255) << 16) | ((uint32_t)(d & 255) << 24);
}

// ============================ int8 2-slice GEMM =================================
// C[M,N] = sA[r]*sB[c]*alpha*(acc1 + acc2/254) (+cbias[c]) (+rbias[r])
// where acc1 = q1A.q1B, acc2 = q1A.q2B + q2A.q1B.  A [M,K] int8 x2, B [N,K] int8 x2.
// Block tile 128x128x64, 16 warps (warp 32x32), 3-stage cp.async.
// smem tile: 128 rows x 64B (+16B pad) = 10240 B; stage = 4 tiles = 40960 B.
#define T_TILE 10240
#define STG_B  40960
#define SMEM_BYTES (3 * STG_B)

__device__ __forceinline__ void load_stage_q(uint32_t st,
    const int8_t* __restrict__ A1, const int8_t* __restrict__ A2, int lda, int m0,
    const int8_t* __restrict__ B1, const int8_t* __restrict__ B2, int ldb, int n0,
    int k0, int tid)
{
    int r  = tid >> 2;            // 0..127
    int cw = tid & 3;             // 16B chunk
    uint32_t soff = (uint32_t)(r * 80 + cw * 16);
    size_t ga = (size_t)(m0 + r) * lda + k0 + cw * 16;
    size_t gb = (size_t)(n0 + r) * ldb + k0 + cw * 16;
    cp_async16(st +              soff, A1 + ga);
    cp_async16(st + T_TILE +     soff, A2 + ga);
    cp_async16(st + 2 * T_TILE + soff, B1 + gb);
    cp_async16(st + 3 * T_TILE + soff, B2 + gb);
}

template<bool CBIAS, bool RBIAS>
__global__ __launch_bounds__(512, 1)
void gemm_s8(const int8_t* __restrict__ A1, const int8_t* __restrict__ A2, int lda,
             const float* __restrict__ sA,
             const int8_t* __restrict__ B1, const int8_t* __restrict__ B2, int ldb,
             const float* __restrict__ sB,
             int K, float* __restrict__ C, int ldc, float alpha,
             const float* __restrict__ cbias, const float* __restrict__ rbias)
{
    extern __shared__ __align__(16) char smem[];
    const uint32_t sbase = smem_u32(smem);
    const int tid = threadIdx.x, wid = tid >> 5, lane = tid & 31;
    const int m0 = blockIdx.y * 128, n0 = blockIdx.x * 128;
    const int wm = wid & 3;            // 0..3 (M, 32 rows)
    const int wn = wid >> 2;           // 0..3 (N, 32 cols)

    const uint32_t aoff = (uint32_t)((wm * 32 + (lane & 15)) * 80 + (lane >> 4) * 16);
    const uint32_t boff = (uint32_t)((wn * 32 + ((lane >> 4) & 1) * 8 + (lane & 7)) * 80
                                     + ((lane >> 3) & 1) * 16);

    int acc1[2][4][4], acc2[2][4][4];
#pragma unroll
    for (int i = 0; i < 2; i++)
#pragma unroll
        for (int j = 0; j < 4; j++)
#pragma unroll
            for (int q = 0; q < 4; q++) { acc1[i][j][q] = 0; acc2[i][j][q] = 0; }

    const int nc = K >> 6;   // 64 int8 per chunk

    load_stage_q(sbase, A1, A2, lda, m0, B1, B2, ldb, n0, 0, tid);
    CP_COMMIT();
    if (nc > 1) load_stage_q(sbase + STG_B, A1, A2, lda, m0, B1, B2, ldb, n0, 64, tid);
    CP_COMMIT();

#pragma unroll 1
    for (int c = 0; c < nc; c++) {
        CP_WAIT1();
        __syncthreads();
        int cn = c + 2;
        if (cn < nc)
            load_stage_q(sbase + (uint32_t)(cn % 3) * STG_B, A1, A2, lda, m0, B1, B2, ldb, n0, cn * 64, tid);
        CP_COMMIT();

        const uint32_t st  = sbase + (uint32_t)(c % 3) * STG_B;
        const uint32_t sA1 = st, sA2 = st + T_TILE;
        const uint32_t sB1 = st + 2 * T_TILE, sB2 = st + 3 * T_TILE;
#pragma unroll
        for (int ks = 0; ks < 2; ks++) {       // each ks = k32 int8
            uint32_t a1[2][4], a2[2][4];
#pragma unroll
            for (int mi = 0; mi < 2; mi++) {
                uint32_t off = aoff + (uint32_t)(mi * 1280 + ks * 32);
                LDSM_X4(a1[mi], sA1 + off);
                LDSM_X4(a2[mi], sA2 + off);
            }
#pragma unroll
            for (int p = 0; p < 2; p++) {
                uint32_t b1[4], b2[4];
                uint32_t off = boff + (uint32_t)(p * 1280 + ks * 32);
                LDSM_X4(b1, sB1 + off);
                LDSM_X4(b2, sB2 + off);
#pragma unroll
                for (int mi = 0; mi < 2; mi++) {
                    MMA_S8(acc1[mi][2 * p + 0], a1[mi], b1[0], b1[1]);
                    MMA_S8(acc1[mi][2 * p + 1], a1[mi], b1[2], b1[3]);
                    MMA_S8(acc2[mi][2 * p + 0], a1[mi], b2[0], b2[1]);
                    MMA_S8(acc2[mi][2 * p + 1], a1[mi], b2[2], b2[3]);
                    MMA_S8(acc2[mi][2 * p + 0], a2[mi], b1[0], b1[1]);
                    MMA_S8(acc2[mi][2 * p + 1], a2[mi], b1[2], b1[3]);
                }
            }
        }
    }

    // ---- epilogue
    const float inv254 = 1.f / 254.f;
#pragma unroll
    for (int mi = 0; mi < 2; mi++) {
        const int r0 = m0 + wm * 32 + mi * 16 + (lane >> 2);
        const int r1 = r0 + 8;
        const float sa0 = sA[r0] * alpha, sa1 = sA[r1] * alpha;
        float rb0 = 0.f, rb1 = 0.f;
        if (RBIAS) { rb0 = rbias[r0]; rb1 = rbias[r1]; }
#pragma unroll
        for (int ni = 0; ni < 4; ni++) {
            const int col = n0 + wn * 32 + ni * 8 + 2 * (lane & 3);
            const float sb0 = sB[col], sb1 = sB[col + 1];
            float v0 = ((float)acc1[mi][ni][0] + (float)acc2[mi][ni][0] * inv254) * sa0 * sb0;
            float v1 = ((float)acc1[mi][ni][1] + (float)acc2[mi][ni][1] * inv254) * sa0 * sb1;
            float v2 = ((float)acc1[mi][ni][2] + (float)acc2[mi][ni][2] * inv254) * sa1 * sb0;
            float v3 = ((float)acc1[mi][ni][3] + (float)acc2[mi][ni][3] * inv254) * sa1 * sb1;
            if (CBIAS) {
                float b0 = cbias[col], b1 = cbias[col + 1];
                v0 += b0; v1 += b1; v2 += b0; v3 += b1;
            }
            if (RBIAS) { v0 += rb0; v1 += rb0; v2 += rb1; v3 += rb1; }
            *reinterpret_cast<float2*>(C + (size_t)r0 * ldc + col) = make_float2(v0, v1);
            *reinterpret_cast<float2*>(C + (size_t)r1 * ldc + col) = make_float2(v2, v3);
        }
    }
}

// ============================ row quantize (f32 -> 2x int8 + scale) =============
__global__ __launch_bounds__(256)
void rowquant_kernel(const float* __restrict__ X, int N,
                     int8_t* __restrict__ q1, int8_t* __restrict__ q2,
                     float* __restrict__ scale)
{
    __shared__ __align__(16) float srow[8192];
    __shared__ float red[8], mxsh;
    const int row = blockIdx.x;
    const int t = threadIdx.x, lane = t & 31, w = t >> 5;
    const float4* xg = reinterpret_cast<const float4*>(X + (size_t)row * N);
    float4* ss = reinterpret_cast<float4*>(srow);
    const int n4 = N >> 2;

    float m = 0.f;
    for (int i = t; i < n4; i += 256) {
        float4 v = xg[i];
        ss[i] = v;
        m = fmaxf(m, fmaxf(fmaxf(fabsf(v.x), fabsf(v.y)), fmaxf(fabsf(v.z), fabsf(v.w))));
    }
#pragma unroll
    for (int off = 16; off > 0; off >>= 1) m = fmaxf(m, __shfl_xor_sync(0xffffffffu, m, off));
    if (lane == 0) red[w] = m;
    __syncthreads();
    if (t == 0) {
        float mm = red[0];
#pragma unroll
        for (int i = 1; i < 8; i++) mm = fmaxf(mm, red[i]);
        mxsh = mm;
        scale[row] = mm * (1.f / 127.f);
    }
    __syncthreads();
    const float mx = mxsh;
    const float inv = mx > 0.f ? 127.f / mx : 0.f;

    uint32_t* o1 = reinterpret_cast<uint32_t*>(q1 + (size_t)row * N);
    uint32_t* o2 = reinterpret_cast<uint32_t*>(q2 + (size_t)row * N);
    for (int i = t; i < n4; i += 256) {
        float4 v = ss[i];
        float y0 = v.x * inv, y1 = v.y * inv, y2 = v.z * inv, y3 = v.w * inv;
        int a0 = __float2int_rn(y0), a1 = __float2int_rn(y1);
        int a2 = __float2int_rn(y2), a3 = __float2int_rn(y3);
        int c0 = __float2int_rn((y0 - a0) * 254.f), c1 = __float2int_rn((y1 - a1) * 254.f);
        int c2 = __float2int_rn((y2 - a2) * 254.f), c3 = __float2int_rn((y3 - a3) * 254.f);
        o1[i] = pack4(a0, a1, a2, a3);
        o2[i] = pack4(c0, c1, c2, c3);
    }
}

// ============================ fused softmax + int8 quantize =====================
// reads S row, computes max, e=exp(s-max), sum; writes qE1/qE2 (y=e*127),
// sE[row] = 1/(127*sum).
__global__ __launch_bounds__(256)
void softmax_row_kernel(const float* __restrict__ S,
                        int8_t* __restrict__ qE1, int8_t* __restrict__ qE2,
                        float* __restrict__ sE)
{
    __shared__ __align__(16) float srow[N_BANK];
    __shared__ float redm[8], reds[8], Msh;
    const int row = blockIdx.x;
    const float4* sg = reinterpret_cast<const float4*>(S + (size_t)row * N_BANK);
    float4* ss = reinterpret_cast<float4*>(srow);
    const int t = threadIdx.x, lane = t & 31, w = t >> 5;

    float m = -1e30f;
#pragma unroll
    for (int it = 0; it < 8; it++) {
        int i = t + it * 256;
        float4 v = sg[i];
        ss[i] = v;
        m = fmaxf(m, fmaxf(fmaxf(v.x, v.y), fmaxf(v.z, v.w)));
    }
#pragma unroll
    for (int off = 16; off > 0; off >>= 1) m = fmaxf(m, __shfl_xor_sync(0xffffffffu, m, off));
    if (lane == 0) redm[w] = m;
    __syncthreads();
    if (t == 0) {
        float mm = redm[0];
#pragma unroll
        for (int i = 1; i < 8; i++) mm = fmaxf(mm, redm[i]);
        Msh = mm;
    }
    __syncthreads();
    const float M = Msh;

    uint32_t* o1 = reinterpret_cast<uint32_t*>(qE1 + (size_t)row * N_BANK);
    uint32_t* o2 = reinterpret_cast<uint32_t*>(qE2 + (size_t)row * N_BANK);
    float s = 0.f;
#pragma unroll
    for (int it = 0; it < 8; it++) {
        int i = t + it * 256;
        float4 v = ss[i];
        float e0 = __expf(v.x - M), e1 = __expf(v.y - M);
        float e2 = __expf(v.z - M), e3 = __expf(v.w - M);
        s += e0 + e1 + e2 + e3;
        float y0 = e0 * 127.f, y1 = e1 * 127.f, y2 = e2 * 127.f, y3 = e3 * 127.f;
        int a0 = __float2int_rn(y0), a1 = __float2int_rn(y1);
        int a2 = __float2int_rn(y2), a3 = __float2int_rn(y3);
        int c0 = __float2int_rn((y0 - a0) * 254.f), c1 = __float2int_rn((y1 - a1) * 254.f);
        int c2 = __float2int_rn((y2 - a2) * 254.f), c3 = __float2int_rn((y3 - a3) * 254.f);
        o1[i] = pack4(a0, a1, a2, a3);
        o2[i] = pack4(c0, c1, c2, c3);
    }
#pragma unroll
    for (int off = 16; off > 0; off >>= 1) s += __shfl_xor_sync(0xffffffffu, s, off);
    if (lane == 0) reds[w] = s;
    __syncthreads();
    if (t == 0) {
        float ss2 = 0.f;
#pragma unroll
        for (int i = 0; i < 8; i++) ss2 += reds[i];
        sE[row] = 1.f / (127.f * ss2);
    }
}

// ============================ gate + LN + PReLU + quantize ======================
__global__ __launch_bounds__(256)
void gate_ln_kernel(const float* __restrict__ F,
                    const float* __restrict__ ln_w, const float* __restrict__ ln_b,
                    const float* __restrict__ prelu_a,
                    int8_t* __restrict__ qX1, int8_t* __restrict__ qX2,
                    float* __restrict__ sX)
{
    const int row = blockIdx.x;
    const int t = threadIdx.x, lane = t & 31, w = t >> 5;
    const float4 f1 = reinterpret_cast<const float4*>(F + (size_t)row * LATENT)[t];
    const float4 f2 = reinterpret_cast<const float4*>(F + (size_t)(N_ROIS + row) * LATENT)[t];
    float4 c;
    c.x = f1.x * f2.x; c.y = f1.y * f2.y; c.z = f1.z * f2.z; c.w = f1.w * f2.w;

    __shared__ float red[8], mu_sh, var_sh, mx_sh;
    float s = c.x + c.y + c.z + c.w;
#pragma unroll
    for (int off = 16; off > 0; off >>= 1) s += __shfl_xor_sync(0xffffffffu, s, off);
    if (lane == 0) red[w] = s;
    __syncthreads();
    if (t == 0) {
        float ss = 0.f;
#pragma unroll
        for (int i = 0; i < 8; i++) ss += red[i];
        mu_sh = ss * (1.f / LATENT);
    }
    __syncthreads();
    const float mu = mu_sh;
    float dx = c.x - mu, dy = c.y - mu, dz = c.z - mu, dw = c.w - mu;
    float sq = dx * dx + dy * dy + dz * dz + dw * dw;
#pragma unroll
    for (int off = 16; off > 0; off >>= 1) sq += __shfl_xor_sync(0xffffffffu, sq, off);
    __syncthreads();
    if (lane == 0) red[w] = sq;
    __syncthreads();
    if (t == 0) {
        float ss = 0.f;
#pragma unroll
        for (int i = 0; i < 8; i++) ss += red[i];
        var_sh = ss * (1.f / LATENT);
    }
    __syncthreads();
    const float inv = rsqrtf(var_sh + LN_EPS);
    const float slope = prelu_a[0];
    const float4 wv = reinterpret_cast<const float4*>(ln_w)[t];
    const float4 bv = reinterpret_cast<const float4*>(ln_b)[t];
    float4 x;
    x.x = dx * inv * wv.x + bv.x;  x.y = dy * inv * wv.y + bv.y;
    x.z = dz * inv * wv.z + bv.z;  x.w = dw * inv * wv.w + bv.w;
    x.x = x.x >= 0.f ? x.x : slope * x.x;
    x.y = x.y >= 0.f ? x.y : slope * x.y;
    x.z = x.z >= 0.f ? x.z : slope * x.z;
    x.w = x.w >= 0.f ? x.w : slope * x.w;

    // row max |x|
    float m = fmaxf(fmaxf(fabsf(x.x), fabsf(x.y)), fmaxf(fabsf(x.z), fabsf(x.w)));
#pragma unroll
    for (int off = 16; off > 0; off >>= 1) m = fmaxf(m, __shfl_xor_sync(0xffffffffu, m, off));
    __syncthreads();
    if (lane == 0) red[w] = m;
    __syncthreads();
    if (t == 0) {
        float mm = red[0];
#pragma unroll
        for (int i = 1; i < 8; i++) mm = fmaxf(mm, red[i]);
        mx_sh = mm;
        sX[row] = mm * (1.f / 127.f);
    }
    __syncthreads();
    const float qinv = mx_sh > 0.f ? 127.f / mx_sh : 0.f;

    float y0 = x.x * qinv, y1 = x.y * qinv, y2 = x.z * qinv, y3 = x.w * qinv;
    int a0 = __float2int_rn(y0), a1 = __float2int_rn(y1);
    int a2 = __float2int_rn(y2), a3 = __float2int_rn(y3);
    int c0 = __float2int_rn((y0 - a0) * 254.f), c1 = __float2int_rn((y1 - a1) * 254.f);
    int c2 = __float2int_rn((y2 - a2) * 254.f), c3 = __float2int_rn((y3 - a3) * 254.f);
    reinterpret_cast<uint32_t*>(qX1 + (size_t)row * LATENT)[t] = pack4(a0, a1, a2, a3);
    reinterpret_cast<uint32_t*>(qX2 + (size_t)row * LATENT)[t] = pack4(c0, c1, c2, c3);
}

// ============================ launch ============================================
static float* symf(const void* s) { void* p; cudaGetSymbolAddress(&p, s); return (float*)p; }
static int8_t* symq(const void* s) { void* p; cudaGetSymbolAddress(&p, s); return (int8_t*)p; }

extern "C" void kernel_launch(void* const* d_in, const int* in_sizes, int n_in,
                              void* d_out, int out_size)
{
    const float* feat     = (const float*)d_in[0];
    const float* key_bank = (const float*)d_in[1];
    const float* Wc1 = (const float*)d_in[2];  const float* bc1 = (const float*)d_in[3];
    const float* Wc2 = (const float*)d_in[4];  const float* bc2 = (const float*)d_in[5];
    const float* Wc3 = (const float*)d_in[6];  const float* bc3 = (const float*)d_in[7];
    const float* Wd1 = (const float*)d_in[8];  const float* bd1 = (const float*)d_in[9];
    const float* Wd2 = (const float*)d_in[10]; const float* bd2 = (const float*)d_in[11];
    const float* Wd3 = (const float*)d_in[12]; const float* bd3 = (const float*)d_in[13];
    const float* ln_w = (const float*)d_in[14];
    const float* ln_b = (const float*)d_in[15];
    const float* prelu_a = (const float*)d_in[16];
    const float* Wffn = (const float*)d_in[17];
    const float* bffn = (const float*)d_in[18];
    float* out = (float*)d_out;

    int8_t *qF1 = symq(&g_qF1), *qF2 = symq(&g_qF2);
    int8_t *qKB1 = symq(&g_qKB1), *qKB2 = symq(&g_qKB2);
    int8_t *qW1 = symq(&g_qW1), *qW2 = symq(&g_qW2);
    int8_t *qWf1 = symq(&g_qWf1), *qWf2 = symq(&g_qWf2);
    int8_t *qQ1 = symq(&g_qQ1), *qQ2 = symq(&g_qQ2);
    int8_t *qK1 = symq(&g_qK1), *qK2 = symq(&g_qK2);
    int8_t *qV1 = symq(&g_qV1), *qV2 = symq(&g_qV2);
    int8_t *qE1 = symq(&g_qE1), *qE2 = symq(&g_qE2);
    int8_t *qX1 = symq(&g_qX1), *qX2 = symq(&g_qX2);
    float *Qf = symf(&g_Qf), *Kf = symf(&g_Kf), *Vtf = symf(&g_Vtf);
    float *S = symf(&g_S), *F = symf(&g_F);
    float *sF = symf(&g_sF), *sKB = symf(&g_sKB), *sW = symf(&g_sW), *sWf = symf(&g_sWf);
    float *sQ = symf(&g_sQ), *sK = symf(&g_sK), *sV = symf(&g_sV);
    float *sE = symf(&g_sE), *sX = symf(&g_sX);

    cudaFuncSetAttribute(gemm_s8<true,false>,  cudaFuncAttributeMaxDynamicSharedMemorySize, SMEM_BYTES);
    cudaFuncSetAttribute(gemm_s8<false,true>,  cudaFuncAttributeMaxDynamicSharedMemorySize, SMEM_BYTES);
    cudaFuncSetAttribute(gemm_s8<false,false>, cudaFuncAttributeMaxDynamicSharedMemorySize, SMEM_BYTES);

    const dim3 g512(1), blk(512), blk256(256);

    // ---- quantize inputs (per-row 2-slice int8)
    rowquant_kernel<<<N_ROIS, blk256>>>(feat, QDIM, qF1, qF2, sF);
    rowquant_kernel<<<N_BANK, blk256>>>(key_bank, DIM_IN, qKB1, qKB2, sKB);
    const float* Ws[6] = { Wc1, Wd1, Wc2, Wd2, Wc3, Wd3 };
    for (int i = 0; i < 6; i++)
        rowquant_kernel<<<LATENT, blk256>>>(Ws[i], QDIM, qW1 + i * WSZ, qW2 + i * WSZ, sW + i * LATENT);
    rowquant_kernel<<<DIM_IN, blk256>>>(Wffn, LATENT, qWf1, qWf2, sWf);

    const size_t QO = (size_t)N_ROIS * LATENT;
    const size_t KO = (size_t)N_BANK * LATENT;
    const size_t VO = (size_t)LATENT * N_BANK;
    const size_t SO = (size_t)N_ROIS * N_BANK;

    // ---- Q projections -> f32, then quantize
    gemm_s8<true,false><<<dim3(8, 32), blk, SMEM_BYTES>>>(qF1, qF2, QDIM, sF,
        qW1 + 0 * WSZ, qW2 + 0 * WSZ, QDIM, sW + 0 * LATENT, QDIM, Qf, LATENT, 1.f, bc1, nullptr);
    gemm_s8<true,false><<<dim3(8, 32), blk, SMEM_BYTES>>>(qF1, qF2, QDIM, sF,
        qW1 + 1 * WSZ, qW2 + 1 * WSZ, QDIM, sW + 1 * LATENT, QDIM, Qf + QO, LATENT, 1.f, bd1, nullptr);
    // ---- K projections
    gemm_s8<true,false><<<dim3(8, 64), blk, SMEM_BYTES>>>(qKB1, qKB2, DIM_IN, sKB,
        qW1 + 2 * WSZ, qW2 + 2 * WSZ, DIM_IN, sW + 2 * LATENT, DIM_IN, Kf, LATENT, 1.f, bc2, nullptr);
    gemm_s8<true,false><<<dim3(8, 64), blk, SMEM_BYTES>>>(qKB1, qKB2, DIM_IN, sKB,
        qW1 + 3 * WSZ, qW2 + 3 * WSZ, DIM_IN, sW + 3 * LATENT, DIM_IN, Kf + KO, LATENT, 1.f, bd2, nullptr);
    // ---- Vt projections: Vt[l,m] = W3[l].kb[m] + b3[l]
    gemm_s8<false,true><<<dim3(64, 8), blk, SMEM_BYTES>>>(qW1 + 4 * WSZ, qW2 + 4 * WSZ, DIM_IN, sW + 4 * LATENT,
        qKB1, qKB2, DIM_IN, sKB, DIM_IN, Vtf, N_BANK, 1.f, nullptr, bc3);
    gemm_s8<false,true><<<dim3(64, 8), blk, SMEM_BYTES>>>(qW1 + 5 * WSZ, qW2 + 5 * WSZ, DIM_IN, sW + 5 * LATENT,
        qKB1, qKB2, DIM_IN, sKB, DIM_IN, Vtf + VO, N_BANK, 1.f, nullptr, bd3);

    // ---- quantize Q, K, Vt
    rowquant_kernel<<<2 * N_ROIS, blk256>>>(Qf, LATENT, qQ1, qQ2, sQ);
    rowquant_kernel<<<2 * N_BANK, blk256>>>(Kf, LATENT, qK1, qK2, sK);
    rowquant_kernel<<<2 * LATENT, blk256>>>(Vtf, N_BANK, qV1, qV2, sV);

    // ---- scores: S = (Q.K^T)/32
    gemm_s8<false,false><<<dim3(64, 32), blk, SMEM_BYTES>>>(qQ1, qQ2, LATENT, sQ,
        qK1, qK2, LATENT, sK, LATENT, S, N_BANK, 0.03125f, nullptr, nullptr);
    gemm_s8<false,false><<<dim3(64, 32), blk, SMEM_BYTES>>>(qQ1 + QO, qQ2 + QO, LATENT, sQ + N_ROIS,
        qK1 + KO, qK2 + KO, LATENT, sK + N_BANK, LATENT, S + SO, N_BANK, 0.03125f, nullptr, nullptr);

    // ---- fused softmax + quantize E
    softmax_row_kernel<<<2 * N_ROIS, blk256>>>(S, qE1, qE2, sE);

    // ---- PV: F = softmax(S).V  (scales folded: sA = 1/(127*rsum), sB = sV)
    gemm_s8<false,false><<<dim3(8, 32), blk, SMEM_BYTES>>>(qE1, qE2, N_BANK, sE,
        qV1, qV2, N_BANK, sV, N_BANK, F, LATENT, 1.f, nullptr, nullptr);
    gemm_s8<false,false><<<dim3(8, 32), blk, SMEM_BYTES>>>(qE1 + SO, qE2 + SO, N_BANK, sE + N_ROIS,
        qV1 + VO, qV2 + VO, N_BANK, sV + LATENT, N_BANK, F + QO, LATENT, 1.f, nullptr, nullptr);

    // ---- gate + LN + PReLU + quantize X
    gate_ln_kernel<<<N_ROIS, blk256>>>(F, ln_w, ln_b, prelu_a, qX1, qX2, sX);

    // ---- FFN: out = X.Wffn^T + bffn
    gemm_s8<true,false><<<dim3(16, 32), blk, SMEM_BYTES>>>(qX1, qX2, LATENT, sX,
        qWf1, qWf2, LATENT, sWf, LATENT, out, DIM_IN, 1.f, bffn, nullptr);
}

// round 6
// speedup vs baseline: 2.6021x; 2.6021x over previous
#include <cuda_runtime.h>
#include <cuda_bf16.h>
#include <cstdint>
#include <math.h>

#define DIM_IN 2048
#define QDIM   2048
#define LATENT 1024
#define N_ROIS 4096
#define N_BANK 8192
#define LN_EPS 1e-5f

// ============================ static scratch ====================================
__device__ __nv_bfloat16 g_feat_h[(size_t)N_ROIS * QDIM];
__device__ __nv_bfloat16 g_feat_l[(size_t)N_ROIS * QDIM];
__device__ __nv_bfloat16 g_kb_h[(size_t)N_BANK * DIM_IN];
__device__ __nv_bfloat16 g_kb_l[(size_t)N_BANK * DIM_IN];
#define WSZ ((size_t)LATENT * QDIM)
__device__ __nv_bfloat16 g_W_h[7 * WSZ];
__device__ __nv_bfloat16 g_W_l[7 * WSZ];
__device__ __nv_bfloat16 g_Q_h[(size_t)2 * N_ROIS * LATENT];
__device__ __nv_bfloat16 g_Q_l[(size_t)2 * N_ROIS * LATENT];
__device__ __nv_bfloat16 g_K_h[(size_t)2 * N_BANK * LATENT];
__device__ __nv_bfloat16 g_K_l[(size_t)2 * N_BANK * LATENT];
__device__ __nv_bfloat16 g_Vt_h[(size_t)2 * LATENT * N_BANK];
__device__ __nv_bfloat16 g_Vt_l[(size_t)2 * LATENT * N_BANK];
__device__ float         g_S  [(size_t)2 * N_ROIS * N_BANK];
__device__ __nv_bfloat16 g_E_h[(size_t)2 * N_ROIS * N_BANK];
__device__ __nv_bfloat16 g_E_l[(size_t)2 * N_ROIS * N_BANK];
__device__ float         g_F  [(size_t)2 * N_ROIS * LATENT];
__device__ __nv_bfloat16 g_X_h[(size_t)N_ROIS * LATENT];
__device__ __nv_bfloat16 g_X_l[(size_t)N_ROIS * LATENT];
__device__ float g_rsum[2 * N_ROIS];

// ============================ PTX helpers =======================================
__device__ __forceinline__ uint32_t smem_u32(const void* p) {
    uint32_t a;
    asm("{ .reg .u64 t; cvta.to.shared.u64 t, %1; cvt.u32.u64 %0, t; }" : "=r"(a) : "l"(p));
    return a;
}
__device__ __forceinline__ void cp_async16(uint32_t s, const void* g) {
    asm volatile("cp.async.cg.shared.global [%0], [%1], 16;\n" :: "r"(s), "l"(g));
}
#define CP_COMMIT() asm volatile("cp.async.commit_group;\n" ::: "memory")
#define CP_WAIT1()  asm volatile("cp.async.wait_group 1;\n" ::: "memory")

#define LDSM_X4(r, a)                                                               \
    asm volatile("ldmatrix.sync.aligned.m8n8.x4.shared.b16 {%0,%1,%2,%3}, [%4];"    \
        : "=r"((r)[0]), "=r"((r)[1]), "=r"((r)[2]), "=r"((r)[3]) : "r"(a))

#define MMA_BF16(c, a, b0, b1)                                                      \
    asm volatile("mma.sync.aligned.m16n8k16.row.col.f32.bf16.bf16.f32 "             \
        "{%0,%1,%2,%3}, {%4,%5,%6,%7}, {%8,%9}, {%0,%1,%2,%3};"                     \
        : "+f"((c)[0]), "+f"((c)[1]), "+f"((c)[2]), "+f"((c)[3])                    \
        : "r"((a)[0]), "r"((a)[1]), "r"((a)[2]), "r"((a)[3]), "r"(b0), "r"(b1))

// ============================ tiled split-bf16 MMA GEMM =========================
// C[M,N] = A[M,K] * B[N,K]^T; A,B as bf16 hi/lo pairs; fp32 accum via
// 3 MMAs (hi*hi + hi*lo + lo*hi).
// MODE 0: split bf16 out, col-bias | 1: split out, row-bias | 2: f32 *alpha
// MODE 3: f32 *1/rsum[row]        | 4: f32 +col-bias
//
// Block tile 128x256x32, 8 warps, WARP TILE 64x64 (2 M-warps x 4 N-warps),
// 3-stage cp.async. High MMA:LDSM ratio (96:16 per warp k16-step), 128 f32
// accumulator regs, 32 independent acc chains per warp.
#define A_TILE_B 10240
#define B_TILE_B 20480
#define STAGE_B  61440
#define SMEM_BYTES (3 * STAGE_B)

__device__ __forceinline__ void load_stage_g(uint32_t st,
    const __nv_bfloat16* __restrict__ Ah, const __nv_bfloat16* __restrict__ Al,
    int lda, int m0,
    const __nv_bfloat16* __restrict__ Bh, const __nv_bfloat16* __restrict__ Bl,
    int ldb, int n0, int k0, int tid)
{
#pragma unroll
    for (int it = 0; it < 2; ++it) {   // A: 128 rows x 4 x16B (hi+lo)
        int id = tid + it * 256;       // 0..511
        int r  = id >> 2;
        int cw = id & 3;
        uint32_t soff = (uint32_t)(r * 80 + cw * 16);
        size_t ga = (size_t)(m0 + r) * lda + k0 + cw * 8;
        cp_async16(st +            soff, Ah + ga);
        cp_async16(st + A_TILE_B + soff, Al + ga);
    }
#pragma unroll
    for (int it = 0; it < 4; ++it) {   // B: 256 rows
        int id = tid + it * 256;       // 0..1023
        int r  = id >> 2;
        int cw = id & 3;
        uint32_t soff = (uint32_t)(r * 80 + cw * 16);
        size_t gb = (size_t)(n0 + r) * ldb + k0 + cw * 8;
        cp_async16(st + 2 * A_TILE_B +            soff, Bh + gb);
        cp_async16(st + 2 * A_TILE_B + B_TILE_B + soff, Bl + gb);
    }
}

template<int MODE>
__global__ __launch_bounds__(256, 1)
void gemm_bf16x3(const __nv_bfloat16* __restrict__ Ah, const __nv_bfloat16* __restrict__ Al, int lda,
                 const __nv_bfloat16* __restrict__ Bh, const __nv_bfloat16* __restrict__ Bl, int ldb,
                 int K,
                 float* __restrict__ Cf,
                 __nv_bfloat16* __restrict__ Ch, __nv_bfloat16* __restrict__ Cl, int ldc,
                 float alpha, const float* __restrict__ bias, const float* __restrict__ rsum)
{
    extern __shared__ __align__(16) char smem[];
    const uint32_t sbase = smem_u32(smem);
    const int tid = threadIdx.x, wid = tid >> 5, lane = tid & 31;
    const int m0 = blockIdx.y * 128, n0 = blockIdx.x * 256;
    const int wm = wid & 1;            // 0..1  (M, 64 rows)
    const int wn = wid >> 1;           // 0..3  (N, 64 cols)

    const uint32_t aoff = (uint32_t)((wm * 64 + (lane & 15)) * 80 + (lane >> 4) * 16);
    const uint32_t boff = (uint32_t)((wn * 64 + ((lane >> 4) & 1) * 8 + (lane & 7)) * 80
                                     + ((lane >> 3) & 1) * 16);

    // acc[mi][p][n8*4+q] : 4*4*8 = 128 f32
    float acc[4][4][8];
#pragma unroll
    for (int i = 0; i < 4; i++)
#pragma unroll
        for (int j = 0; j < 4; j++)
#pragma unroll
            for (int q = 0; q < 8; q++) acc[i][j][q] = 0.f;

    const int nc = K >> 5;

    load_stage_g(sbase, Ah, Al, lda, m0, Bh, Bl, ldb, n0, 0, tid);
    CP_COMMIT();
    if (nc > 1) load_stage_g(sbase + STAGE_B, Ah, Al, lda, m0, Bh, Bl, ldb, n0, 32, tid);
    CP_COMMIT();

#pragma unroll 1
    for (int c = 0; c < nc; c++) {
        CP_WAIT1();
        __syncthreads();
        int cn = c + 2;
        if (cn < nc)
            load_stage_g(sbase + (uint32_t)(cn % 3) * STAGE_B, Ah, Al, lda, m0, Bh, Bl, ldb, n0, cn * 32, tid);
        CP_COMMIT();

        const uint32_t st  = sbase + (uint32_t)(c % 3) * STAGE_B;
        const uint32_t sAh = st, sAl = st + A_TILE_B;
        const uint32_t sBh = st + 2 * A_TILE_B, sBl = st + 2 * A_TILE_B + B_TILE_B;
#pragma unroll
        for (int ks = 0; ks < 2; ks++) {
            uint32_t ah[4][4], al[4][4];
#pragma unroll
            for (int mi = 0; mi < 4; mi++) {
                uint32_t off = aoff + (uint32_t)(mi * 1280 + ks * 32);
                LDSM_X4(ah[mi], sAh + off);
                LDSM_X4(al[mi], sAl + off);
            }
#pragma unroll
            for (int p = 0; p < 4; p++) {
                uint32_t bh[4], bl[4];
                uint32_t off = boff + (uint32_t)(p * 1280 + ks * 32);
                LDSM_X4(bh, sBh + off);
                LDSM_X4(bl, sBl + off);
#pragma unroll
                for (int mi = 0; mi < 4; mi++) {
                    MMA_BF16((acc[mi][p] + 0), ah[mi], bh[0], bh[1]);
                    MMA_BF16((acc[mi][p] + 4), ah[mi], bh[2], bh[3]);
                    MMA_BF16((acc[mi][p] + 0), ah[mi], bl[0], bl[1]);
                    MMA_BF16((acc[mi][p] + 4), ah[mi], bl[2], bl[3]);
                    MMA_BF16((acc[mi][p] + 0), al[mi], bh[0], bh[1]);
                    MMA_BF16((acc[mi][p] + 4), al[mi], bh[2], bh[3]);
                }
            }
        }
    }

    // ---- epilogue: fragment (mi,p,n8): rows r0,r0+8; cols col,col+1
#pragma unroll
    for (int mi = 0; mi < 4; mi++) {
        const int r0 = m0 + wm * 64 + mi * 16 + (lane >> 2);
        const int r1 = r0 + 8;
        float s0 = 1.f, s1 = 1.f, rb0 = 0.f, rb1 = 0.f;
        if (MODE == 3) { s0 = 1.f / rsum[r0]; s1 = 1.f / rsum[r1]; }
        if (MODE == 1) { rb0 = bias[r0]; rb1 = bias[r1]; }
#pragma unroll
        for (int p = 0; p < 4; p++) {
#pragma unroll
            for (int n8 = 0; n8 < 2; n8++) {
                const int col = n0 + wn * 64 + p * 16 + n8 * 8 + 2 * (lane & 3);
                const float* a4 = acc[mi][p] + n8 * 4;
                float v0 = a4[0], v1 = a4[1], v2 = a4[2], v3 = a4[3];
                if (MODE == 2) { v0 *= alpha; v1 *= alpha; v2 *= alpha; v3 *= alpha; }
                if (MODE == 3) { v0 *= s0; v1 *= s0; v2 *= s1; v3 *= s1; }
                if (MODE == 0 || MODE == 4) {
                    float b0 = bias[col], b1 = bias[col + 1];
                    v0 += b0; v1 += b1; v2 += b0; v3 += b1;
                }
                if (MODE == 1) { v0 += rb0; v1 += rb0; v2 += rb1; v3 += rb1; }

                if (MODE == 2 || MODE == 3 || MODE == 4) {
                    *reinterpret_cast<float2*>(Cf + (size_t)r0 * ldc + col) = make_float2(v0, v1);
                    *reinterpret_cast<float2*>(Cf + (size_t)r1 * ldc + col) = make_float2(v2, v3);
                } else {
                    __nv_bfloat16 h0 = __float2bfloat16(v0), h1 = __float2bfloat16(v1);
                    __nv_bfloat16 h2 = __float2bfloat16(v2), h3 = __float2bfloat16(v3);
                    *reinterpret_cast<__nv_bfloat162*>(Ch + (size_t)r0 * ldc + col) = __halves2bfloat162(h0, h1);
                    *reinterpret_cast<__nv_bfloat162*>(Ch + (size_t)r1 * ldc + col) = __halves2bfloat162(h2, h3);
                    *reinterpret_cast<__nv_bfloat162*>(Cl + (size_t)r0 * ldc + col) =
                        __halves2bfloat162(__float2bfloat16(v0 - __bfloat162float(h0)),
                                           __float2bfloat16(v1 - __bfloat162float(h1)));
                    *reinterpret_cast<__nv_bfloat162*>(Cl + (size_t)r1 * ldc + col) =
                        __halves2bfloat162(__float2bfloat16(v2 - __bfloat162float(h2)),
                                           __float2bfloat16(v3 - __bfloat162float(h3)));
                }
            }
        }
    }
}

// ============================ aux kernels =======================================
__global__ __launch_bounds__(256)
void split4_kernel(const float4* __restrict__ s, __nv_bfloat162* __restrict__ h,
                   __nv_bfloat162* __restrict__ l, int n4)
{
    for (int i = blockIdx.x * blockDim.x + threadIdx.x; i < n4; i += gridDim.x * blockDim.x) {
        float4 v = s[i];
        __nv_bfloat16 hx = __float2bfloat16(v.x), hy = __float2bfloat16(v.y);
        __nv_bfloat16 hz = __float2bfloat16(v.z), hw = __float2bfloat16(v.w);
        h[2 * i + 0] = __halves2bfloat162(hx, hy);
        h[2 * i + 1] = __halves2bfloat162(hz, hw);
        l[2 * i + 0] = __halves2bfloat162(__float2bfloat16(v.x - __bfloat162float(hx)),
                                          __float2bfloat16(v.y - __bfloat162float(hy)));
        l[2 * i + 1] = __halves2bfloat162(__float2bfloat16(v.z - __bfloat162float(hz)),
                                          __float2bfloat16(v.w - __bfloat162float(hw)));
    }
}

// fused: per-row max + exp-split + sum; S row cached in smem (one read of S).
__global__ __launch_bounds__(256)
void softmax_row_kernel(const float* __restrict__ S,
                        __nv_bfloat162* __restrict__ Eh, __nv_bfloat162* __restrict__ El,
                        float* __restrict__ rsum)
{
    __shared__ __align__(16) float srow[N_BANK];
    __shared__ float redm[8], reds[8], Msh;
    const int row = blockIdx.x;
    const float4* sg = reinterpret_cast<const float4*>(S + (size_t)row * N_BANK);
    float4* ss = reinterpret_cast<float4*>(srow);
    const int t = threadIdx.x, lane = t & 31, w = t >> 5;

    float m = -1e30f;
#pragma unroll
    for (int it = 0; it < 8; it++) {
        int i = t + it * 256;
        float4 v = sg[i];
        ss[i] = v;
        m = fmaxf(m, fmaxf(fmaxf(v.x, v.y), fmaxf(v.z, v.w)));
    }
#pragma unroll
    for (int off = 16; off > 0; off >>= 1) m = fmaxf(m, __shfl_xor_sync(0xffffffffu, m, off));
    if (lane == 0) redm[w] = m;
    __syncthreads();
    if (t == 0) {
        float mm = redm[0];
#pragma unroll
        for (int i = 1; i < 8; i++) mm = fmaxf(mm, redm[i]);
        Msh = mm;
    }
    __syncthreads();
    const float M = Msh;

    __nv_bfloat162* ehr = Eh + (size_t)row * (N_BANK / 2);
    __nv_bfloat162* elr = El + (size_t)row * (N_BANK / 2);
    float s = 0.f;
#pragma unroll
    for (int it = 0; it < 8; it++) {
        int i = t + it * 256;
        float4 v = ss[i];
        float e0 = __expf(v.x - M), e1 = __expf(v.y - M);
        float e2 = __expf(v.z - M), e3 = __expf(v.w - M);
        s += e0 + e1 + e2 + e3;
        __nv_bfloat16 h0 = __float2bfloat16(e0), h1 = __float2bfloat16(e1);
        __nv_bfloat16 h2 = __float2bfloat16(e2), h3 = __float2bfloat16(e3);
        ehr[2 * i + 0] = __halves2bfloat162(h0, h1);
        ehr[2 * i + 1] = __halves2bfloat162(h2, h3);
        elr[2 * i + 0] = __halves2bfloat162(__float2bfloat16(e0 - __bfloat162float(h0)),
                                            __float2bfloat16(e1 - __bfloat162float(h1)));
        elr[2 * i + 1] = __halves2bfloat162(__float2bfloat16(e2 - __bfloat162float(h2)),
                                            __float2bfloat16(e3 - __bfloat162float(h3)));
    }
#pragma unroll
    for (int off = 16; off > 0; off >>= 1) s += __shfl_xor_sync(0xffffffffu, s, off);
    if (lane == 0) reds[w] = s;
    __syncthreads();
    if (t == 0) {
        float ss2 = 0.f;
#pragma unroll
        for (int i = 0; i < 8; i++) ss2 += reds[i];
        rsum[row] = ss2;
    }
}

__global__ __launch_bounds__(256)
void gate_ln_kernel(const float* __restrict__ F,
                    const float* __restrict__ ln_w, const float* __restrict__ ln_b,
                    const float* __restrict__ prelu_a,
                    __nv_bfloat16* __restrict__ Xh, __nv_bfloat16* __restrict__ Xl)
{
    const int row = blockIdx.x;
    const int t = threadIdx.x, lane = t & 31, w = t >> 5;
    const float4 f1 = reinterpret_cast<const float4*>(F + (size_t)row * LATENT)[t];
    const float4 f2 = reinterpret_cast<const float4*>(F + (size_t)(N_ROIS + row) * LATENT)[t];
    float4 c;
    c.x = f1.x * f2.x; c.y = f1.y * f2.y; c.z = f1.z * f2.z; c.w = f1.w * f2.w;

    __shared__ float red[8], mu_sh, var_sh;
    float s = c.x + c.y + c.z + c.w;
#pragma unroll
    for (int off = 16; off > 0; off >>= 1) s += __shfl_xor_sync(0xffffffffu, s, off);
    if (lane == 0) red[w] = s;
    __syncthreads();
    if (t == 0) {
        float ss = 0.f;
#pragma unroll
        for (int i = 0; i < 8; i++) ss += red[i];
        mu_sh = ss * (1.f / LATENT);
    }
    __syncthreads();
    const float mu = mu_sh;
    float dx = c.x - mu, dy = c.y - mu, dz = c.z - mu, dw = c.w - mu;
    float sq = dx * dx + dy * dy + dz * dz + dw * dw;
#pragma unroll
    for (int off = 16; off > 0; off >>= 1) sq += __shfl_xor_sync(0xffffffffu, sq, off);
    __syncthreads();
    if (lane == 0) red[w] = sq;
    __syncthreads();
    if (t == 0) {
        float ss = 0.f;
#pragma unroll
        for (int i = 0; i < 8; i++) ss += red[i];
        var_sh = ss * (1.f / LATENT);
    }
    __syncthreads();
    const float inv = rsqrtf(var_sh + LN_EPS);
    const float slope = prelu_a[0];
    const float4 wv = reinterpret_cast<const float4*>(ln_w)[t];
    const float4 bv = reinterpret_cast<const float4*>(ln_b)[t];
    float4 x;
    x.x = dx * inv * wv.x + bv.x;  x.y = dy * inv * wv.y + bv.y;
    x.z = dz * inv * wv.z + bv.z;  x.w = dw * inv * wv.w + bv.w;
    x.x = x.x >= 0.f ? x.x : slope * x.x;
    x.y = x.y >= 0.f ? x.y : slope * x.y;
    x.z = x.z >= 0.f ? x.z : slope * x.z;
    x.w = x.w >= 0.f ? x.w : slope * x.w;

    __nv_bfloat16 h0 = __float2bfloat16(x.x), h1 = __float2bfloat16(x.y);
    __nv_bfloat16 h2 = __float2bfloat16(x.z), h3 = __float2bfloat16(x.w);
    __nv_bfloat162* hp = reinterpret_cast<__nv_bfloat162*>(Xh + (size_t)row * LATENT);
    __nv_bfloat162* lp = reinterpret_cast<__nv_bfloat162*>(Xl + (size_t)row * LATENT);
    hp[2 * t + 0] = __halves2bfloat162(h0, h1);
    hp[2 * t + 1] = __halves2bfloat162(h2, h3);
    lp[2 * t + 0] = __halves2bfloat162(__float2bfloat16(x.x - __bfloat162float(h0)),
                                       __float2bfloat16(x.y - __bfloat162float(h1)));
    lp[2 * t + 1] = __halves2bfloat162(__float2bfloat16(x.z - __bfloat162float(h2)),
                                       __float2bfloat16(x.w - __bfloat162float(h3)));
}

// ============================ launch ============================================
static float* symf(const void* s) { void* p; cudaGetSymbolAddress(&p, s); return (float*)p; }
static __nv_bfloat16* symb(const void* s) { void* p; cudaGetSymbolAddress(&p, s); return (__nv_bfloat16*)p; }

extern "C" void kernel_launch(void* const* d_in, const int* in_sizes, int n_in,
                              void* d_out, int out_size)
{
    const float* feat     = (const float*)d_in[0];
    const float* key_bank = (const float*)d_in[1];
    const float* Wc1 = (const float*)d_in[2];  const float* bc1 = (const float*)d_in[3];
    const float* Wc2 = (const float*)d_in[4];  const float* bc2 = (const float*)d_in[5];
    const float* Wc3 = (const float*)d_in[6];  const float* bc3 = (const float*)d_in[7];
    const float* Wd1 = (const float*)d_in[8];  const float* bd1 = (const float*)d_in[9];
    const float* Wd2 = (const float*)d_in[10]; const float* bd2 = (const float*)d_in[11];
    const float* Wd3 = (const float*)d_in[12]; const float* bd3 = (const float*)d_in[13];
    const float* ln_w = (const float*)d_in[14];
    const float* ln_b = (const float*)d_in[15];
    const float* prelu_a = (const float*)d_in[16];
    const float* Wffn = (const float*)d_in[17];
    const float* bffn = (const float*)d_in[18];
    float* out = (float*)d_out;

    __nv_bfloat16 *feat_h = symb(&g_feat_h), *feat_l = symb(&g_feat_l);
    __nv_bfloat16 *kb_h = symb(&g_kb_h), *kb_l = symb(&g_kb_l);
    __nv_bfloat16 *W_h = symb(&g_W_h), *W_l = symb(&g_W_l);
    __nv_bfloat16 *Q_h = symb(&g_Q_h), *Q_l = symb(&g_Q_l);
    __nv_bfloat16 *K_h = symb(&g_K_h), *K_l = symb(&g_K_l);
    __nv_bfloat16 *Vt_h = symb(&g_Vt_h), *Vt_l = symb(&g_Vt_l);
    __nv_bfloat16 *E_h = symb(&g_E_h), *E_l = symb(&g_E_l);
    __nv_bfloat16 *X_h = symb(&g_X_h), *X_l = symb(&g_X_l);
    float *S = symf(&g_S), *F = symf(&g_F), *RS = symf(&g_rsum);

    cudaFuncSetAttribute(gemm_bf16x3<0>, cudaFuncAttributeMaxDynamicSharedMemorySize, SMEM_BYTES);
    cudaFuncSetAttribute(gemm_bf16x3<1>, cudaFuncAttributeMaxDynamicSharedMemorySize, SMEM_BYTES);
    cudaFuncSetAttribute(gemm_bf16x3<2>, cudaFuncAttributeMaxDynamicSharedMemorySize, SMEM_BYTES);
    cudaFuncSetAttribute(gemm_bf16x3<3>, cudaFuncAttributeMaxDynamicSharedMemorySize, SMEM_BYTES);
    cudaFuncSetAttribute(gemm_bf16x3<4>, cudaFuncAttributeMaxDynamicSharedMemorySize, SMEM_BYTES);

    const dim3 blk(256);
    const int SG = 1184;

    // ---- split-convert inputs & weights
    split4_kernel<<<SG, blk>>>((const float4*)feat, (__nv_bfloat162*)feat_h, (__nv_bfloat162*)feat_l, (int)((size_t)N_ROIS * QDIM / 4));
    split4_kernel<<<SG, blk>>>((const float4*)key_bank, (__nv_bfloat162*)kb_h, (__nv_bfloat162*)kb_l, (int)((size_t)N_BANK * DIM_IN / 4));
    const float* Ws[7] = { Wc1, Wd1, Wc2, Wd2, Wc3, Wd3, Wffn };
    for (int i = 0; i < 7; i++)
        split4_kernel<<<SG, blk>>>((const float4*)Ws[i],
            (__nv_bfloat162*)(W_h + i * WSZ), (__nv_bfloat162*)(W_l + i * WSZ), (int)(WSZ / 4));

    const size_t QO = (size_t)N_ROIS * LATENT;
    const size_t KO = (size_t)N_BANK * LATENT;
    const size_t VO = (size_t)LATENT * N_BANK;
    const size_t SO = (size_t)N_ROIS * N_BANK;

    // ---- Q projections: [4096,1024] = feat @ W^T    MODE0
    gemm_bf16x3<0><<<dim3(4, 32), blk, SMEM_BYTES>>>(feat_h, feat_l, QDIM,
        W_h + 0 * WSZ, W_l + 0 * WSZ, QDIM, QDIM, nullptr, Q_h, Q_l, LATENT, 0.f, bc1, nullptr);
    gemm_bf16x3<0><<<dim3(4, 32), blk, SMEM_BYTES>>>(feat_h, feat_l, QDIM,
        W_h + 1 * WSZ, W_l + 1 * WSZ, QDIM, QDIM, nullptr, Q_h + QO, Q_l + QO, LATENT, 0.f, bd1, nullptr);
    // ---- K projections: [8192,1024]                 MODE0
    gemm_bf16x3<0><<<dim3(4, 64), blk, SMEM_BYTES>>>(kb_h, kb_l, DIM_IN,
        W_h + 2 * WSZ, W_l + 2 * WSZ, DIM_IN, DIM_IN, nullptr, K_h, K_l, LATENT, 0.f, bc2, nullptr);
    gemm_bf16x3<0><<<dim3(4, 64), blk, SMEM_BYTES>>>(kb_h, kb_l, DIM_IN,
        W_h + 3 * WSZ, W_l + 3 * WSZ, DIM_IN, DIM_IN, nullptr, K_h + KO, K_l + KO, LATENT, 0.f, bd2, nullptr);
    // ---- Vt projections: [1024,8192] = W @ key_bank^T   MODE1 (row bias)
    gemm_bf16x3<1><<<dim3(32, 8), blk, SMEM_BYTES>>>(W_h + 4 * WSZ, W_l + 4 * WSZ, DIM_IN,
        kb_h, kb_l, DIM_IN, DIM_IN, nullptr, Vt_h, Vt_l, N_BANK, 0.f, bc3, nullptr);
    gemm_bf16x3<1><<<dim3(32, 8), blk, SMEM_BYTES>>>(W_h + 5 * WSZ, W_l + 5 * WSZ, DIM_IN,
        kb_h, kb_l, DIM_IN, DIM_IN, nullptr, Vt_h + VO, Vt_l + VO, N_BANK, 0.f, bd3, nullptr);

    // ---- scores: S = (Q K^T) / 32    MODE2
    gemm_bf16x3<2><<<dim3(32, 32), blk, SMEM_BYTES>>>(Q_h, Q_l, LATENT,
        K_h, K_l, LATENT, LATENT, S, nullptr, nullptr, N_BANK, 0.03125f, nullptr, nullptr);
    gemm_bf16x3<2><<<dim3(32, 32), blk, SMEM_BYTES>>>(Q_h + QO, Q_l + QO, LATENT,
        K_h + KO, K_l + KO, LATENT, LATENT, S + SO, nullptr, nullptr, N_BANK, 0.03125f, nullptr, nullptr);

    // ---- fused softmax (max + exp-split + sum), one read of S
    softmax_row_kernel<<<2 * N_ROIS, blk>>>(S, (__nv_bfloat162*)E_h, (__nv_bfloat162*)E_l, RS);

    // ---- PV: F = (E Vt^T) * 1/rsum    MODE3
    gemm_bf16x3<3><<<dim3(4, 32), blk, SMEM_BYTES>>>(E_h, E_l, N_BANK,
        Vt_h, Vt_l, N_BANK, N_BANK, F, nullptr, nullptr, LATENT, 0.f, nullptr, RS);
    gemm_bf16x3<3><<<dim3(4, 32), blk, SMEM_BYTES>>>(E_h + SO, E_l + SO, N_BANK,
        Vt_h + VO, Vt_l + VO, N_BANK, N_BANK, F + QO, nullptr, nullptr, LATENT, 0.f, nullptr, RS + N_ROIS);

    // ---- gate + LN + PReLU -> X split
    gate_ln_kernel<<<N_ROIS, blk>>>(F, ln_w, ln_b, prelu_a, X_h, X_l);

    // ---- FFN: out = X Wffn^T + bffn   MODE4
    gemm_bf16x3<4><<<dim3(8, 32), blk, SMEM_BYTES>>>(X_h, X_l, LATENT,
        W_h + 6 * WSZ, W_l + 6 * WSZ, LATENT, LATENT, out, nullptr, nullptr, DIM_IN, 0.f, bffn, nullptr);
}

// round 7
// speedup vs baseline: 3.6989x; 1.4215x over previous
#include <cuda_runtime.h>
#include <cuda_fp16.h>
#include <cstdint>
#include <math.h>

#define DIM_IN 2048
#define QDIM   2048
#define LATENT 1024
#define N_ROIS 4096
#define N_BANK 8192
#define LN_EPS 1e-5f

// ============================ static scratch ====================================
__device__ __half g_feat_h[(size_t)N_ROIS * QDIM];
__device__ __half g_feat_l[(size_t)N_ROIS * QDIM];
__device__ __half g_kb_h[(size_t)N_BANK * DIM_IN];
__device__ __half g_kb_l[(size_t)N_BANK * DIM_IN];
#define WSZ ((size_t)LATENT * QDIM)
__device__ __half g_W_h[7 * WSZ];
__device__ __half g_W_l[7 * WSZ];
__device__ __half g_Q_h[(size_t)2 * N_ROIS * LATENT];
__device__ __half g_Q_l[(size_t)2 * N_ROIS * LATENT];
__device__ __half g_K_h[(size_t)2 * N_BANK * LATENT];
__device__ __half g_Vt_h[(size_t)2 * LATENT * N_BANK];
__device__ float  g_S  [(size_t)2 * N_ROIS * N_BANK];
__device__ __half g_E_h[(size_t)2 * N_ROIS * N_BANK];
__device__ __half g_E_l[(size_t)2 * N_ROIS * N_BANK];
__device__ float  g_F  [(size_t)2 * N_ROIS * LATENT];
__device__ __half g_X_h[(size_t)N_ROIS * LATENT];
__device__ __half g_X_l[(size_t)N_ROIS * LATENT];
__device__ float g_rsum[2 * N_ROIS];

// ============================ PTX helpers =======================================
__device__ __forceinline__ uint32_t smem_u32(const void* p) {
    uint32_t a;
    asm("{ .reg .u64 t; cvta.to.shared.u64 t, %1; cvt.u32.u64 %0, t; }" : "=r"(a) : "l"(p));
    return a;
}
__device__ __forceinline__ void cp_async16(uint32_t s, const void* g) {
    asm volatile("cp.async.cg.shared.global [%0], [%1], 16;\n" :: "r"(s), "l"(g));
}
#define CP_COMMIT() asm volatile("cp.async.commit_group;\n" ::: "memory")
#define CP_WAIT1()  asm volatile("cp.async.wait_group 1;\n" ::: "memory")

#define LDSM_X4(r, a)                                                               \
    asm volatile("ldmatrix.sync.aligned.m8n8.x4.shared.b16 {%0,%1,%2,%3}, [%4];"    \
        : "=r"((r)[0]), "=r"((r)[1]), "=r"((r)[2]), "=r"((r)[3]) : "r"(a))

#define MMA_F16(c, a, b0, b1)                                                       \
    asm volatile("mma.sync.aligned.m16n8k16.row.col.f32.f16.f16.f32 "               \
        "{%0,%1,%2,%3}, {%4,%5,%6,%7}, {%8,%9}, {%0,%1,%2,%3};"                     \
        : "+f"((c)[0]), "+f"((c)[1]), "+f"((c)[2]), "+f"((c)[3])                    \
        : "r"((a)[0]), "r"((a)[1]), "r"((a)[2]), "r"((a)[3]), "r"(b0), "r"(b1))

__device__ __forceinline__ void split16(float x, __half& h, __half& l) {
    h = __float2half_rn(x);
    l = __float2half_rn(x - __half2float(h));
}

// ============================ tiled split-fp16 MMA GEMM =========================
// C[M,N] = A[M,K] * B[N,K]^T, fp32 accumulate.
// T2=true : A = hiA+loA (fp16 pair), B = hiB only -> 2 MMAs (hihi + loA*hiB)
// T2=false: A,B both hi/lo pairs -> 3 MMAs (hihi + hiA*loB + loA*hiB)
// MODE 0: fp16 split out (+col-bias) | 1: fp16 split out (+row-bias)
// MODE 2: f32 out *alpha | 3: f32 out *1/rsum[row] | 4: f32 out +col-bias
// SLO: store lo plane in MODE0/1.
// Block tile 128x256x32, 8 warps, warp tile 64x64, 3-stage cp.async.
#define A_TILE_B 10240
#define B_TILE_B 20480

template<bool T2>
__device__ __forceinline__ void load_stage_g(uint32_t st,
    const __half* __restrict__ Ah, const __half* __restrict__ Al, int lda, int m0,
    const __half* __restrict__ Bh, const __half* __restrict__ Bl, int ldb, int n0,
    int k0, int tid)
{
#pragma unroll
    for (int it = 0; it < 2; ++it) {   // A: 128 rows, hi+lo
        int id = tid + it * 256;
        int r  = id >> 2;
        int cw = id & 3;
        uint32_t soff = (uint32_t)(r * 80 + cw * 16);
        size_t ga = (size_t)(m0 + r) * lda + k0 + cw * 8;
        cp_async16(st +            soff, Ah + ga);
        cp_async16(st + A_TILE_B + soff, Al + ga);
    }
#pragma unroll
    for (int it = 0; it < 4; ++it) {   // B: 256 rows
        int id = tid + it * 256;
        int r  = id >> 2;
        int cw = id & 3;
        uint32_t soff = (uint32_t)(r * 80 + cw * 16);
        size_t gb = (size_t)(n0 + r) * ldb + k0 + cw * 8;
        cp_async16(st + 2 * A_TILE_B + soff, Bh + gb);
        if (!T2) cp_async16(st + 2 * A_TILE_B + B_TILE_B + soff, Bl + gb);
    }
}

template<int MODE, bool T2, bool SLO>
__global__ __launch_bounds__(256, 1)
void gemm_f16(const __half* __restrict__ Ah, const __half* __restrict__ Al, int lda,
              const __half* __restrict__ Bh, const __half* __restrict__ Bl, int ldb,
              int K,
              float* __restrict__ Cf,
              __half* __restrict__ Ch, __half* __restrict__ Cl, int ldc,
              float alpha, const float* __restrict__ bias, const float* __restrict__ rsum)
{
    constexpr uint32_t STAGE_B = T2 ? (2 * A_TILE_B + B_TILE_B)
                                    : (2 * A_TILE_B + 2 * B_TILE_B);
    extern __shared__ __align__(16) char smem[];
    const uint32_t sbase = smem_u32(smem);
    const int tid = threadIdx.x, wid = tid >> 5, lane = tid & 31;
    const int m0 = blockIdx.y * 128, n0 = blockIdx.x * 256;
    const int wm = wid & 1;            // 0..1  (M, 64 rows)
    const int wn = wid >> 1;           // 0..3  (N, 64 cols)

    const uint32_t aoff = (uint32_t)((wm * 64 + (lane & 15)) * 80 + (lane >> 4) * 16);
    const uint32_t boff = (uint32_t)((wn * 64 + ((lane >> 4) & 1) * 8 + (lane & 7)) * 80
                                     + ((lane >> 3) & 1) * 16);

    float acc[4][4][8];
#pragma unroll
    for (int i = 0; i < 4; i++)
#pragma unroll
        for (int j = 0; j < 4; j++)
#pragma unroll
            for (int q = 0; q < 8; q++) acc[i][j][q] = 0.f;

    const int nc = K >> 5;

    load_stage_g<T2>(sbase, Ah, Al, lda, m0, Bh, Bl, ldb, n0, 0, tid);
    CP_COMMIT();
    if (nc > 1) load_stage_g<T2>(sbase + STAGE_B, Ah, Al, lda, m0, Bh, Bl, ldb, n0, 32, tid);
    CP_COMMIT();

#pragma unroll 1
    for (int c = 0; c < nc; c++) {
        CP_WAIT1();
        __syncthreads();
        int cn = c + 2;
        if (cn < nc)
            load_stage_g<T2>(sbase + (uint32_t)(cn % 3) * STAGE_B, Ah, Al, lda, m0, Bh, Bl, ldb, n0, cn * 32, tid);
        CP_COMMIT();

        const uint32_t st  = sbase + (uint32_t)(c % 3) * STAGE_B;
        const uint32_t sAh = st, sAl = st + A_TILE_B;
        const uint32_t sBh = st + 2 * A_TILE_B;
        const uint32_t sBl = st + 2 * A_TILE_B + B_TILE_B;
#pragma unroll
        for (int ks = 0; ks < 2; ks++) {
            uint32_t ah[4][4], al[4][4];
#pragma unroll
            for (int mi = 0; mi < 4; mi++) {
                uint32_t off = aoff + (uint32_t)(mi * 1280 + ks * 32);
                LDSM_X4(ah[mi], sAh + off);
                LDSM_X4(al[mi], sAl + off);
            }
#pragma unroll
            for (int p = 0; p < 4; p++) {
                uint32_t off = boff + (uint32_t)(p * 1280 + ks * 32);
                uint32_t bh[4];
                LDSM_X4(bh, sBh + off);
                if (T2) {
#pragma unroll
                    for (int mi = 0; mi < 4; mi++) {
                        MMA_F16((acc[mi][p] + 0), ah[mi], bh[0], bh[1]);
                        MMA_F16((acc[mi][p] + 4), ah[mi], bh[2], bh[3]);
                        MMA_F16((acc[mi][p] + 0), al[mi], bh[0], bh[1]);
                        MMA_F16((acc[mi][p] + 4), al[mi], bh[2], bh[3]);
                    }
                } else {
                    uint32_t bl[4];
                    LDSM_X4(bl, sBl + off);
#pragma unroll
                    for (int mi = 0; mi < 4; mi++) {
                        MMA_F16((acc[mi][p] + 0), ah[mi], bh[0], bh[1]);
                        MMA_F16((acc[mi][p] + 4), ah[mi], bh[2], bh[3]);
                        MMA_F16((acc[mi][p] + 0), ah[mi], bl[0], bl[1]);
                        MMA_F16((acc[mi][p] + 4), ah[mi], bl[2], bl[3]);
                        MMA_F16((acc[mi][p] + 0), al[mi], bh[0], bh[1]);
                        MMA_F16((acc[mi][p] + 4), al[mi], bh[2], bh[3]);
                    }
                }
            }
        }
    }

    // ---- epilogue
#pragma unroll
    for (int mi = 0; mi < 4; mi++) {
        const int r0 = m0 + wm * 64 + mi * 16 + (lane >> 2);
        const int r1 = r0 + 8;
        float s0 = 1.f, s1 = 1.f, rb0 = 0.f, rb1 = 0.f;
        if (MODE == 3) { s0 = 1.f / rsum[r0]; s1 = 1.f / rsum[r1]; }
        if (MODE == 1) { rb0 = bias[r0]; rb1 = bias[r1]; }
#pragma unroll
        for (int p = 0; p < 4; p++) {
#pragma unroll
            for (int n8 = 0; n8 < 2; n8++) {
                const int col = n0 + wn * 64 + p * 16 + n8 * 8 + 2 * (lane & 3);
                const float* a4 = acc[mi][p] + n8 * 4;
                float v0 = a4[0], v1 = a4[1], v2 = a4[2], v3 = a4[3];
                if (MODE == 2) { v0 *= alpha; v1 *= alpha; v2 *= alpha; v3 *= alpha; }
                if (MODE == 3) { v0 *= s0; v1 *= s0; v2 *= s1; v3 *= s1; }
                if (MODE == 0 || MODE == 4) {
                    float b0 = bias[col], b1 = bias[col + 1];
                    v0 += b0; v1 += b1; v2 += b0; v3 += b1;
                }
                if (MODE == 1) { v0 += rb0; v1 += rb0; v2 += rb1; v3 += rb1; }

                if (MODE == 2 || MODE == 3 || MODE == 4) {
                    *reinterpret_cast<float2*>(Cf + (size_t)r0 * ldc + col) = make_float2(v0, v1);
                    *reinterpret_cast<float2*>(Cf + (size_t)r1 * ldc + col) = make_float2(v2, v3);
                } else {
                    __half h0, h1, h2, h3, l0, l1, l2, l3;
                    split16(v0, h0, l0); split16(v1, h1, l1);
                    split16(v2, h2, l2); split16(v3, h3, l3);
                    *reinterpret_cast<__half2*>(Ch + (size_t)r0 * ldc + col) = __halves2half2(h0, h1);
                    *reinterpret_cast<__half2*>(Ch + (size_t)r1 * ldc + col) = __halves2half2(h2, h3);
                    if (SLO) {
                        *reinterpret_cast<__half2*>(Cl + (size_t)r0 * ldc + col) = __halves2half2(l0, l1);
                        *reinterpret_cast<__half2*>(Cl + (size_t)r1 * ldc + col) = __halves2half2(l2, l3);
                    }
                }
            }
        }
    }
}

// ============================ aux kernels =======================================
__global__ __launch_bounds__(256)
void split4_kernel(const float4* __restrict__ s, __half2* __restrict__ h,
                   __half2* __restrict__ l, int n4)
{
    for (int i = blockIdx.x * blockDim.x + threadIdx.x; i < n4; i += gridDim.x * blockDim.x) {
        float4 v = s[i];
        __half hx, hy, hz, hw, lx, ly, lz, lw;
        split16(v.x, hx, lx); split16(v.y, hy, ly);
        split16(v.z, hz, lz); split16(v.w, hw, lw);
        h[2 * i + 0] = __halves2half2(hx, hy);
        h[2 * i + 1] = __halves2half2(hz, hw);
        l[2 * i + 0] = __halves2half2(lx, ly);
        l[2 * i + 1] = __halves2half2(lz, lw);
    }
}

// fused: per-row max + exp (fp16 hi/lo) + sum; S row cached in smem.
__global__ __launch_bounds__(256)
void softmax_row_kernel(const float* __restrict__ S,
                        __half2* __restrict__ Eh, __half2* __restrict__ El,
                        float* __restrict__ rsum)
{
    __shared__ __align__(16) float srow[N_BANK];
    __shared__ float redm[8], reds[8], Msh;
    const int row = blockIdx.x;
    const float4* sg = reinterpret_cast<const float4*>(S + (size_t)row * N_BANK);
    float4* ss = reinterpret_cast<float4*>(srow);
    const int t = threadIdx.x, lane = t & 31, w = t >> 5;

    float m = -1e30f;
#pragma unroll
    for (int it = 0; it < 8; it++) {
        int i = t + it * 256;
        float4 v = sg[i];
        ss[i] = v;
        m = fmaxf(m, fmaxf(fmaxf(v.x, v.y), fmaxf(v.z, v.w)));
    }
#pragma unroll
    for (int off = 16; off > 0; off >>= 1) m = fmaxf(m, __shfl_xor_sync(0xffffffffu, m, off));
    if (lane == 0) redm[w] = m;
    __syncthreads();
    if (t == 0) {
        float mm = redm[0];
#pragma unroll
        for (int i = 1; i < 8; i++) mm = fmaxf(mm, redm[i]);
        Msh = mm;
    }
    __syncthreads();
    const float M = Msh;

    __half2* ehr = Eh + (size_t)row * (N_BANK / 2);
    __half2* elr = El + (size_t)row * (N_BANK / 2);
    float s = 0.f;
#pragma unroll
    for (int it = 0; it < 8; it++) {
        int i = t + it * 256;
        float4 v = ss[i];
        float e0 = __expf(v.x - M), e1 = __expf(v.y - M);
        float e2 = __expf(v.z - M), e3 = __expf(v.w - M);
        s += e0 + e1 + e2 + e3;
        __half h0, h1, h2, h3, l0, l1, l2, l3;
        split16(e0, h0, l0); split16(e1, h1, l1);
        split16(e2, h2, l2); split16(e3, h3, l3);
        ehr[2 * i + 0] = __halves2half2(h0, h1);
        ehr[2 * i + 1] = __halves2half2(h2, h3);
        elr[2 * i + 0] = __halves2half2(l0, l1);
        elr[2 * i + 1] = __halves2half2(l2, l3);
    }
#pragma unroll
    for (int off = 16; off > 0; off >>= 1) s += __shfl_xor_sync(0xffffffffu, s, off);
    if (lane == 0) reds[w] = s;
    __syncthreads();
    if (t == 0) {
        float ss2 = 0.f;
#pragma unroll
        for (int i = 0; i < 8; i++) ss2 += reds[i];
        rsum[row] = ss2;
    }
}

__global__ __launch_bounds__(256)
void gate_ln_kernel(const float* __restrict__ F,
                    const float* __restrict__ ln_w, const float* __restrict__ ln_b,
                    const float* __restrict__ prelu_a,
                    __half* __restrict__ Xh, __half* __restrict__ Xl)
{
    const int row = blockIdx.x;
    const int t = threadIdx.x, lane = t & 31, w = t >> 5;
    const float4 f1 = reinterpret_cast<const float4*>(F + (size_t)row * LATENT)[t];
    const float4 f2 = reinterpret_cast<const float4*>(F + (size_t)(N_ROIS + row) * LATENT)[t];
    float4 c;
    c.x = f1.x * f2.x; c.y = f1.y * f2.y; c.z = f1.z * f2.z; c.w = f1.w * f2.w;

    __shared__ float red[8], mu_sh, var_sh;
    float s = c.x + c.y + c.z + c.w;
#pragma unroll
    for (int off = 16; off > 0; off >>= 1) s += __shfl_xor_sync(0xffffffffu, s, off);
    if (lane == 0) red[w] = s;
    __syncthreads();
    if (t == 0) {
        float ss = 0.f;
#pragma unroll
        for (int i = 0; i < 8; i++) ss += red[i];
        mu_sh = ss * (1.f / LATENT);
    }
    __syncthreads();
    const float mu = mu_sh;
    float dx = c.x - mu, dy = c.y - mu, dz = c.z - mu, dw = c.w - mu;
    float sq = dx * dx + dy * dy + dz * dz + dw * dw;
#pragma unroll
    for (int off = 16; off > 0; off >>= 1) sq += __shfl_xor_sync(0xffffffffu, sq, off);
    __syncthreads();
    if (lane == 0) red[w] = sq;
    __syncthreads();
    if (t == 0) {
        float ss = 0.f;
#pragma unroll
        for (int i = 0; i < 8; i++) ss += red[i];
        var_sh = ss * (1.f / LATENT);
    }
    __syncthreads();
    const float inv = rsqrtf(var_sh + LN_EPS);
    const float slope = prelu_a[0];
    const float4 wv = reinterpret_cast<const float4*>(ln_w)[t];
    const float4 bv = reinterpret_cast<const float4*>(ln_b)[t];
    float4 x;
    x.x = dx * inv * wv.x + bv.x;  x.y = dy * inv * wv.y + bv.y;
    x.z = dz * inv * wv.z + bv.z;  x.w = dw * inv * wv.w + bv.w;
    x.x = x.x >= 0.f ? x.x : slope * x.x;
    x.y = x.y >= 0.f ? x.y : slope * x.y;
    x.z = x.z >= 0.f ? x.z : slope * x.z;
    x.w = x.w >= 0.f ? x.w : slope * x.w;

    __half h0, h1, h2, h3, l0, l1, l2, l3;
    split16(x.x, h0, l0); split16(x.y, h1, l1);
    split16(x.z, h2, l2); split16(x.w, h3, l3);
    __half2* hp = reinterpret_cast<__half2*>(Xh + (size_t)row * LATENT);
    __half2* lp = reinterpret_cast<__half2*>(Xl + (size_t)row * LATENT);
    hp[2 * t + 0] = __halves2half2(h0, h1);
    hp[2 * t + 1] = __halves2half2(h2, h3);
    lp[2 * t + 0] = __halves2half2(l0, l1);
    lp[2 * t + 1] = __halves2half2(l2, l3);
}

// ============================ launch ============================================
static float* symf(const void* s) { void* p; cudaGetSymbolAddress(&p, s); return (float*)p; }
static __half* symh(const void* s) { void* p; cudaGetSymbolAddress(&p, s); return (__half*)p; }

extern "C" void kernel_launch(void* const* d_in, const int* in_sizes, int n_in,
                              void* d_out, int out_size)
{
    const float* feat     = (const float*)d_in[0];
    const float* key_bank = (const float*)d_in[1];
    const float* Wc1 = (const float*)d_in[2];  const float* bc1 = (const float*)d_in[3];
    const float* Wc2 = (const float*)d_in[4];  const float* bc2 = (const float*)d_in[5];
    const float* Wc3 = (const float*)d_in[6];  const float* bc3 = (const float*)d_in[7];
    const float* Wd1 = (const float*)d_in[8];  const float* bd1 = (const float*)d_in[9];
    const float* Wd2 = (const float*)d_in[10]; const float* bd2 = (const float*)d_in[11];
    const float* Wd3 = (const float*)d_in[12]; const float* bd3 = (const float*)d_in[13];
    const float* ln_w = (const float*)d_in[14];
    const float* ln_b = (const float*)d_in[15];
    const float* prelu_a = (const float*)d_in[16];
    const float* Wffn = (const float*)d_in[17];
    const float* bffn = (const float*)d_in[18];
    float* out = (float*)d_out;

    __half *feat_h = symh(&g_feat_h), *feat_l = symh(&g_feat_l);
    __half *kb_h = symh(&g_kb_h), *kb_l = symh(&g_kb_l);
    __half *W_h = symh(&g_W_h), *W_l = symh(&g_W_l);
    __half *Q_h = symh(&g_Q_h), *Q_l = symh(&g_Q_l);
    __half *K_h = symh(&g_K_h);
    __half *Vt_h = symh(&g_Vt_h);
    __half *E_h = symh(&g_E_h), *E_l = symh(&g_E_l);
    __half *X_h = symh(&g_X_h), *X_l = symh(&g_X_l);
    float *S = symf(&g_S), *F = symf(&g_F), *RS = symf(&g_rsum);

    const int SM_T2 = 3 * (2 * A_TILE_B + B_TILE_B);        // 122880
    const int SM_T3 = 3 * (2 * A_TILE_B + 2 * B_TILE_B);    // 184320
    cudaFuncSetAttribute(gemm_f16<0,true,true>,   cudaFuncAttributeMaxDynamicSharedMemorySize, SM_T2);
    cudaFuncSetAttribute(gemm_f16<0,true,false>,  cudaFuncAttributeMaxDynamicSharedMemorySize, SM_T2);
    cudaFuncSetAttribute(gemm_f16<1,true,false>,  cudaFuncAttributeMaxDynamicSharedMemorySize, SM_T2);
    cudaFuncSetAttribute(gemm_f16<2,true,false>,  cudaFuncAttributeMaxDynamicSharedMemorySize, SM_T2);
    cudaFuncSetAttribute(gemm_f16<3,true,false>,  cudaFuncAttributeMaxDynamicSharedMemorySize, SM_T2);
    cudaFuncSetAttribute(gemm_f16<4,false,false>, cudaFuncAttributeMaxDynamicSharedMemorySize, SM_T3);

    const dim3 blk(256);
    const int SG = 1184;

    // ---- split-convert inputs & weights (fp16 hi/lo)
    split4_kernel<<<SG, blk>>>((const float4*)feat, (__half2*)feat_h, (__half2*)feat_l, (int)((size_t)N_ROIS * QDIM / 4));
    split4_kernel<<<SG, blk>>>((const float4*)key_bank, (__half2*)kb_h, (__half2*)kb_l, (int)((size_t)N_BANK * DIM_IN / 4));
    const float* Ws[7] = { Wc1, Wd1, Wc2, Wd2, Wc3, Wd3, Wffn };
    for (int i = 0; i < 7; i++)
        split4_kernel<<<SG, blk>>>((const float4*)Ws[i],
            (__half2*)(W_h + i * WSZ), (__half2*)(W_l + i * WSZ), (int)(WSZ / 4));

    const size_t QO = (size_t)N_ROIS * LATENT;
    const size_t KO = (size_t)N_BANK * LATENT;
    const size_t VO = (size_t)LATENT * N_BANK;
    const size_t SO = (size_t)N_ROIS * N_BANK;

    // ---- Q projections (A=feat split, B=W hi) -> store hi+lo   MODE0, T2, SLO
    gemm_f16<0,true,true><<<dim3(4, 32), blk, SM_T2>>>(feat_h, feat_l, QDIM,
        W_h + 0 * WSZ, nullptr, QDIM, QDIM, nullptr, Q_h, Q_l, LATENT, 0.f, bc1, nullptr);
    gemm_f16<0,true,true><<<dim3(4, 32), blk, SM_T2>>>(feat_h, feat_l, QDIM,
        W_h + 1 * WSZ, nullptr, QDIM, QDIM, nullptr, Q_h + QO, Q_l + QO, LATENT, 0.f, bd1, nullptr);
    // ---- K projections (A=key_bank split, B=W hi) -> hi only
    gemm_f16<0,true,false><<<dim3(4, 64), blk, SM_T2>>>(kb_h, kb_l, DIM_IN,
        W_h + 2 * WSZ, nullptr, DIM_IN, DIM_IN, nullptr, K_h, nullptr, LATENT, 0.f, bc2, nullptr);
    gemm_f16<0,true,false><<<dim3(4, 64), blk, SM_T2>>>(kb_h, kb_l, DIM_IN,
        W_h + 3 * WSZ, nullptr, DIM_IN, DIM_IN, nullptr, K_h + KO, nullptr, LATENT, 0.f, bd2, nullptr);
    // ---- Vt projections (A=W split, B=key_bank hi) -> hi only, row bias
    gemm_f16<1,true,false><<<dim3(32, 8), blk, SM_T2>>>(W_h + 4 * WSZ, W_l + 4 * WSZ, DIM_IN,
        kb_h, nullptr, DIM_IN, DIM_IN, nullptr, Vt_h, nullptr, N_BANK, 0.f, bc3, nullptr);
    gemm_f16<1,true,false><<<dim3(32, 8), blk, SM_T2>>>(W_h + 5 * WSZ, W_l + 5 * WSZ, DIM_IN,
        kb_h, nullptr, DIM_IN, DIM_IN, nullptr, Vt_h + VO, nullptr, N_BANK, 0.f, bd3, nullptr);

    // ---- scores: S = (Q K^T)/32   (A=Q split, B=K hi)   MODE2, T2
    gemm_f16<2,true,false><<<dim3(32, 32), blk, SM_T2>>>(Q_h, Q_l, LATENT,
        K_h, nullptr, LATENT, LATENT, S, nullptr, nullptr, N_BANK, 0.03125f, nullptr, nullptr);
    gemm_f16<2,true,false><<<dim3(32, 32), blk, SM_T2>>>(Q_h + QO, Q_l + QO, LATENT,
        K_h + KO, nullptr, LATENT, LATENT, S + SO, nullptr, nullptr, N_BANK, 0.03125f, nullptr, nullptr);

    // ---- fused softmax (max + exp-split + sum)
    softmax_row_kernel<<<2 * N_ROIS, blk>>>(S, (__half2*)E_h, (__half2*)E_l, RS);

    // ---- PV: F = (E Vt^T)/rsum   (A=E split, B=Vt hi)   MODE3, T2
    gemm_f16<3,true,false><<<dim3(4, 32), blk, SM_T2>>>(E_h, E_l, N_BANK,
        Vt_h, nullptr, N_BANK, N_BANK, F, nullptr, nullptr, LATENT, 0.f, nullptr, RS);
    gemm_f16<3,true,false><<<dim3(4, 32), blk, SM_T2>>>(E_h + SO, E_l + SO, N_BANK,
        Vt_h + VO, nullptr, N_BANK, N_BANK, F + QO, nullptr, nullptr, LATENT, 0.f, nullptr, RS + N_ROIS);

    // ---- gate + LN + PReLU -> X split
    gate_ln_kernel<<<N_ROIS, blk>>>(F, ln_w, ln_b, prelu_a, X_h, X_l);

    // ---- FFN (3-term: A=X split, B=Wffn split)   MODE4, T3
    gemm_f16<4,false,false><<<dim3(8, 32), blk, SM_T3>>>(X_h, X_l, LATENT,
        W_h + 6 * WSZ, W_l + 6 * WSZ, LATENT, LATENT, out, nullptr, nullptr, DIM_IN, 0.f, bffn, nullptr);
}